// round 15
// baseline (speedup 1.0000x reference)
#include <cuda_runtime.h>
#include <cuda_fp16.h>
#include <math.h>
#include <stdint.h>

// Fixed problem shape: n=8192, k=128, h=128
#define N_FIX 8192
#define KDIM 128
#define BM 128
#define BK 32
#define KSPLIT 4
#define KQ (N_FIX / KSPLIT)           // 2048
#define NIT (KQ / BK)                 // 64 iterations per CTA
#define NCTA ((N_FIX / BM) * KSPLIT)  // 256
// smem: B stages [0, 4*8192) ; A double buffer at 32768, 2 x 10240 (128 rows x 80B)
#define A_BASE 32768
#define A_BUFB 10240
#define SMEM_BYTES (A_BASE + 2 * A_BUFB)   // 53248 -> 2 CTAs/SM

// ---------------- device scratch ----------------
__device__ __align__(16) __half g_Cb[(size_t)N_FIX * KDIM];
__device__ float g_d[N_FIX];     // row sums of A (atomic, KSPLIT partials)
__device__ float g_h2[N_FIX];    // ||H_i||^2
__device__ float g_col[KDIM];
__device__ float g_diag[KDIM];
__device__ int g_cnt;

// ---------------- helpers ----------------
__device__ __forceinline__ uint32_t smem_u32(const void* p) {
    uint32_t a;
    asm("{ .reg .u64 t; cvta.to.shared.u64 t, %1; cvt.u32.u64 %0, t; }" : "=r"(a) : "l"(p));
    return a;
}
__device__ __forceinline__ void cp16(uint32_t saddr, const void* gp) {
    unsigned long long g = __cvta_generic_to_global(gp);
    asm volatile("cp.async.cg.shared.global [%0], [%1], 16;" :: "r"(saddr), "l"(g) : "memory");
}
#define CP_COMMIT() asm volatile("cp.async.commit_group;" ::: "memory")
#define CP_WAIT2()  asm volatile("cp.async.wait_group 2;" ::: "memory")

__device__ __forceinline__ uint32_t cvt_h2(float x, float y) {
    __half2 h = __floats2half2_rn(x, y);
    return *reinterpret_cast<uint32_t*>(&h);
}
__device__ __forceinline__ void ldmx4(uint32_t* r, uint32_t addr) {
    asm volatile("ldmatrix.sync.aligned.m8n8.x4.shared.b16 {%0,%1,%2,%3}, [%4];"
                 : "=r"(r[0]), "=r"(r[1]), "=r"(r[2]), "=r"(r[3]) : "r"(addr));
}
__device__ __forceinline__ void ldmx4t(uint32_t& r0, uint32_t& r1, uint32_t& r2,
                                       uint32_t& r3, uint32_t addr) {
    asm volatile("ldmatrix.sync.aligned.m8n8.x4.trans.shared.b16 {%0,%1,%2,%3}, [%4];"
                 : "=r"(r0), "=r"(r1), "=r"(r2), "=r"(r3) : "r"(addr));
}
// f16 MMA with f16 accumulators
__device__ __forceinline__ void mma16816h(uint32_t* d, const uint32_t* a, uint32_t b0,
                                          uint32_t b1) {
    asm volatile(
        "mma.sync.aligned.m16n8k16.row.col.f16.f16.f16.f16 "
        "{%0,%1}, {%2,%3,%4,%5}, {%6,%7}, {%0,%1};"
        : "+r"(d[0]), "+r"(d[1])
        : "r"(a[0]), "r"(a[1]), "r"(a[2]), "r"(a[3]), "r"(b0), "r"(b1));
}

// ---------------- prep: init, C->f16, ||H_i||^2 ----------------
__global__ void __launch_bounds__(256) k_prep(const float* __restrict__ C,
                                              const float* __restrict__ H) {
    const int b = blockIdx.x, tid = threadIdx.x;
    if (b == 0) {
        if (tid < KDIM) { g_col[tid] = 0.0f; g_diag[tid] = 0.0f; }
        if (tid == 0) g_cnt = 0;
    }
    if (tid < 32) g_d[b * 32 + tid] = 0.0f;

    size_t base = ((size_t)b * 256 + tid) * 16;
    const float4* src = reinterpret_cast<const float4*>(C + base);
    uint32_t o[8];
#pragma unroll
    for (int q = 0; q < 4; ++q) {
        float4 v = __ldg(&src[q]);
        o[q * 2 + 0] = cvt_h2(v.x, v.y);
        o[q * 2 + 1] = cvt_h2(v.z, v.w);
    }
    uint4* dst = reinterpret_cast<uint4*>(g_Cb + base);
    dst[0] = make_uint4(o[0], o[1], o[2], o[3]);
    dst[1] = make_uint4(o[4], o[5], o[6], o[7]);

    const int row = b * 32 + (tid >> 3);
    const float4* hp = reinterpret_cast<const float4*>(H + (size_t)row * KDIM + (tid & 7) * 16);
    float h2 = 0.0f;
#pragma unroll
    for (int q = 0; q < 4; ++q) {
        float4 v = __ldg(&hp[q]);
        h2 += v.x * v.x + v.y * v.y + v.z * v.z + v.w * v.w;
    }
    h2 += __shfl_xor_sync(0xffffffffu, h2, 1);
    h2 += __shfl_xor_sync(0xffffffffu, h2, 2);
    h2 += __shfl_xor_sync(0xffffffffu, h2, 4);
    if ((tid & 7) == 0) g_h2[row] = h2;
}

// ---------------- split-K GEMM: A LDG->f16 STS, B cp.async, f16 acc ----------------
__global__ void __launch_bounds__(256, 2) k_gemm(const float* __restrict__ A,
                                                 const float* __restrict__ C,
                                                 const float* __restrict__ papra,
                                                 const int* __restrict__ flag,
                                                 float* __restrict__ out, int out_size) {
    extern __shared__ __align__(1024) char smem[];
    __shared__ float scol[KDIM], sdiag[KDIM], swarp[8];
    __shared__ int is_last;

    const int tid = threadIdx.x, lane = tid & 31, wid = tid >> 5;
    const int wm = wid & 3, wn = wid >> 2;        // 4 M-warps (m32) x 2 N-warps (n64)
    const int rb = blockIdx.x >> 2;               // row block
    const int kh = blockIdx.x & 3;                // K quarter
    const int blockRow = rb * BM;
    const int kbase = kh * KQ;
    const uint32_t su = smem_u32(smem);

    if (tid < KDIM) { scol[tid] = 0.0f; sdiag[tid] = 0.0f; }

    // ---- A LDG/STS mapping: 4 threads/row, 8 fp32 each; rows arow and arow+64 ----
    const int arow = tid >> 2;                    // 0..63
    const int acg = (tid & 3) * 8;                // fp32 col offset in 32-wide tile
    const float* gA0 = A + (size_t)(blockRow + arow) * N_FIX + kbase + acg;
    const float* gA1 = A + (size_t)(blockRow + arow + 64) * N_FIX + kbase + acg;
    const uint32_t stsA0 = (uint32_t)(arow * 80 + (tid & 3) * 16);          // f16 16B
    const uint32_t stsA1 = (uint32_t)((arow + 64) * 80 + (tid & 3) * 16);

    // ---- B cp.async mapping (8KB/stage, 2 chunks/thread) ----
    const int kB0 = tid >> 4, cB0 = tid & 15;
    const uint32_t soB0 = (uint32_t)(kB0 * 256 + ((cB0 * 16) ^ ((kB0 & 7) << 4)));
    const __half* gB0 = g_Cb + (size_t)(kbase + kB0) * KDIM + cB0 * 8;

    // ---- A LDSM offsets (80B stride, conflict-free; validated in R5) ----
    uint32_t aoff[2][2];
    {
        int r = wm * 32 + (lane & 7) + ((lane >> 3) & 1) * 8;
        int ckl = lane >> 4;  // 16B k-half within k16
#pragma unroll
        for (int mt = 0; mt < 2; ++mt)
#pragma unroll
            for (int kq = 0; kq < 2; ++kq)
                aoff[mt][kq] = (uint32_t)A_BASE + (uint32_t)((r + mt * 16) * 80 +
                                                             (kq * 2 + ckl) * 16);
    }
    // ---- B LDSM (trans) offsets ----
    uint32_t boff[4];
    {
        const int mM = lane >> 3, iR = lane & 7;
        const int kkb = (mM & 1) * 8 + iR;
#pragma unroll
        for (int g = 0; g < 4; ++g) {
            int nn = wn * 64 + g * 16 + (mM >> 1) * 8;
            uint32_t off = (uint32_t)(kkb * 256 + nn * 2);
            boff[g] = off ^ ((kkb & 7) << 4);
        }
    }

    // f16 accumulators
    uint32_t acc[2][8][2];
#pragma unroll
    for (int mt = 0; mt < 2; ++mt)
#pragma unroll
        for (int t = 0; t < 8; ++t) { acc[mt][t][0] = 0u; acc[mt][t][1] = 0u; }
    float d0 = 0.0f, d1 = 0.0f;  // row sums (exact fp32) for arow, arow+64

    // A register slots, depth 2: slot s holds tile t with t&1 == s
    float4 s0a[2], s0b[2];  // slot content: rows arow (a) and arow+64 (b), 2 float4 each
    float4 s1a[2], s1b[2];

#define LDG_TILE(t, sa, sb) do {                                             \
        const float4* p0 = reinterpret_cast<const float4*>(gA0 + (size_t)(t) * BK); \
        const float4* p1 = reinterpret_cast<const float4*>(gA1 + (size_t)(t) * BK); \
        sa[0] = __ldg(p0); sa[1] = __ldg(p0 + 1);                            \
        sb[0] = __ldg(p1); sb[1] = __ldg(p1 + 1);                            \
    } while (0)

#define STS_TILE(buf, sa, sb) do {                                           \
        d0 += (sa[0].x + sa[0].y) + (sa[0].z + sa[0].w) +                    \
              (sa[1].x + sa[1].y) + (sa[1].z + sa[1].w);                     \
        d1 += (sb[0].x + sb[0].y) + (sb[0].z + sb[0].w) +                    \
              (sb[1].x + sb[1].y) + (sb[1].z + sb[1].w);                     \
        uint4 u0 = make_uint4(cvt_h2(sa[0].x, sa[0].y), cvt_h2(sa[0].z, sa[0].w), \
                              cvt_h2(sa[1].x, sa[1].y), cvt_h2(sa[1].z, sa[1].w)); \
        uint4 u1 = make_uint4(cvt_h2(sb[0].x, sb[0].y), cvt_h2(sb[0].z, sb[0].w), \
                              cvt_h2(sb[1].x, sb[1].y), cvt_h2(sb[1].z, sb[1].w)); \
        *reinterpret_cast<uint4*>(smem + A_BASE + (buf) * A_BUFB + stsA0) = u0; \
        *reinterpret_cast<uint4*>(smem + A_BASE + (buf) * A_BUFB + stsA1) = u1; \
    } while (0)

    // ---- prologue ----
    LDG_TILE(0, s0a, s0b);
    LDG_TILE(1, s1a, s1b);
    STS_TILE(0, s0a, s0b);       // tile 0 -> abuf0 (+ dsum for tile 0)
    LDG_TILE(2, s0a, s0b);       // slot0 now holds tile 2
    // B stages 0..2
#pragma unroll
    for (int s = 0; s < 3; ++s) {
        cp16(su + s * 8192 + soB0, gB0 + (size_t)s * 4096);
        cp16(su + s * 8192 + soB0 + 4096, gB0 + (size_t)s * 4096 + (size_t)16 * KDIM);
        CP_COMMIT();
    }

    // ---- main loop ----
#pragma unroll 2
    for (int it = 0; it < NIT; ++it) {
        CP_WAIT2();
        __syncthreads();
        const uint32_t abuf = (uint32_t)((it & 1) * A_BUFB);
        const uint32_t bstg = (uint32_t)((it & 3) * 8192);

        // STS tile it+1 (slot (it+1)&1), then refill that slot with tile it+3
        const int nit = it + 1;
        if (nit < NIT) {
            if (nit & 1) { STS_TILE(1, s1a, s1b); } else { STS_TILE(0, s0a, s0b); }
        }
        const int fit = it + 3;
        if (fit < NIT) {
            if (fit & 1) { LDG_TILE(fit, s1a, s1b); } else { LDG_TILE(fit, s0a, s0b); }
        }

#pragma unroll
        for (int kq = 0; kq < 2; ++kq) {
            uint32_t ra[2][4];
            ldmx4(ra[0], su + abuf + aoff[0][kq]);
            ldmx4(ra[1], su + abuf + aoff[1][kq]);
#pragma unroll
            for (int g = 0; g < 4; ++g) {
                uint32_t b0, b1, b2, b3;
                ldmx4t(b0, b1, b2, b3, su + bstg + boff[g] + kq * 4096);
                mma16816h(acc[0][2 * g], ra[0], b0, b1);
                mma16816h(acc[0][2 * g + 1], ra[0], b2, b3);
                mma16816h(acc[1][2 * g], ra[1], b0, b1);
                mma16816h(acc[1][2 * g + 1], ra[1], b2, b3);
            }
        }

        const int pit = it + 3;
        if (pit < NIT) {
            uint32_t sb = su + (pit & 3) * 8192;
            cp16(sb + soB0, gB0 + (size_t)pit * 4096);
            cp16(sb + soB0 + 4096, gB0 + (size_t)pit * 4096 + (size_t)16 * KDIM);
        }
        CP_COMMIT();
    }

    // ---- row sums of A (exact fp32; 4 threads/row, no duplication) ----
    d0 += __shfl_xor_sync(0xffffffffu, d0, 1);
    d0 += __shfl_xor_sync(0xffffffffu, d0, 2);
    d1 += __shfl_xor_sync(0xffffffffu, d1, 1);
    d1 += __shfl_xor_sync(0xffffffffu, d1, 2);
    if ((tid & 3) == 0) {
        atomicAdd(&g_d[blockRow + arow], d0);
        atomicAdd(&g_d[blockRow + arow + 64], d1);
    }

    // ---- colsum(M) and diag partials (unpack f16 acc) ----
    const int r0 = wm * 32 + (lane >> 2);
    const int cb = (lane & 3) * 2;
#pragma unroll
    for (int mt = 0; mt < 2; ++mt)
#pragma unroll
    for (int t = 0; t < 8; ++t) {
        const int cbase = wn * 64 + t * 8 + cb;
        const int row = blockRow + r0 + mt * 16;
        float2 c0 = *reinterpret_cast<const float2*>(C + (size_t)row * KDIM + cbase);
        float2 c1 = *reinterpret_cast<const float2*>(C + (size_t)(row + 8) * KDIM + cbase);
        float2 m0 = __half22float2(*reinterpret_cast<__half2*>(&acc[mt][t][0]));
        float2 m1 = __half22float2(*reinterpret_cast<__half2*>(&acc[mt][t][1]));
        float cs0 = m0.x + m1.x;
        float cs1 = m0.y + m1.y;
        float ds0 = c0.x * m0.x + c1.x * m1.x;
        float ds1 = c0.y * m0.y + c1.y * m1.y;
#pragma unroll
        for (int o = 4; o <= 16; o <<= 1) {
            cs0 += __shfl_xor_sync(0xffffffffu, cs0, o);
            cs1 += __shfl_xor_sync(0xffffffffu, cs1, o);
            ds0 += __shfl_xor_sync(0xffffffffu, ds0, o);
            ds1 += __shfl_xor_sync(0xffffffffu, ds1, o);
        }
        if ((lane >> 2) == 0) {
            atomicAdd(&scol[cbase], cs0);
            atomicAdd(&scol[cbase + 1], cs1);
            atomicAdd(&sdiag[cbase], ds0);
            atomicAdd(&sdiag[cbase + 1], ds1);
        }
    }
    __syncthreads();
    if (tid < KDIM) {
        atomicAdd(&g_col[tid], scol[tid]);
        atomicAdd(&g_diag[tid], sdiag[tid]);
    }

    // ---- last CTA: sA, h_part, entropy, output ----
    if (tid == 0) {
        __threadfence();
        int c = atomicAdd(&g_cnt, 1);
        is_last = (c == NCTA - 1);
    }
    __syncthreads();
    if (is_last) {
        float a1 = 0.0f, a2 = 0.0f;
        for (int i = tid; i < N_FIX; i += 256) {
            float d = __ldcg(&g_d[i]);
            a1 += d * __ldcg(&g_h2[i]);
            a2 += d;
        }
#pragma unroll
        for (int o = 16; o > 0; o >>= 1) {
            a1 += __shfl_xor_sync(0xffffffffu, a1, o);
            a2 += __shfl_xor_sync(0xffffffffu, a2, o);
        }
        if (lane == 0) { swarp[wid] = a1; scol[wid] = a2; }
        __syncthreads();
        float hp = 0.0f, sA = 0.0f;
#pragma unroll
        for (int w = 0; w < 8; ++w) { hp += swarp[w]; sA += scol[w]; }

        float t = 0.0f;
        if (tid < KDIM) {
            float dg = __ldcg(&g_diag[tid]);
            float cl = __ldcg(&g_col[tid]);
            t = dg * log2f(cl / sA + 1e-40f);
        }
#pragma unroll
        for (int o = 16; o > 0; o >>= 1) t += __shfl_xor_sync(0xffffffffu, t, o);
        __syncthreads();
        if (lane == 0) sdiag[wid] = t;
        __syncthreads();
        if (tid == 0) {
            float total = (sdiag[0] + sdiag[1] + sdiag[2] + sdiag[3]) / sA;
            int fl = flag ? *flag : 20;
            float pw = papra ? *papra : 1.0f;
            if (fl > 10) total += pw * hp;
            out[0] = total;
            if (out_size > 1) out[1] = hp;
        }
    }
}

extern "C" void kernel_launch(void* const* d_in, const int* in_sizes, int n_in,
                              void* d_out, int out_size) {
    const float* A = (const float*)d_in[0];
    const float* C = (const float*)d_in[1];
    const float* H = (const float*)d_in[2];
    const float* papra = (n_in > 3) ? (const float*)d_in[3] : nullptr;
    const int* flag = (n_in > 4) ? (const int*)d_in[4] : nullptr;

    cudaFuncSetAttribute(k_gemm, cudaFuncAttributeMaxDynamicSharedMemorySize, SMEM_BYTES);

    k_prep<<<N_FIX / 32, 256>>>(C, H);
    k_gemm<<<NCTA, 256, SMEM_BYTES>>>(A, C, papra, flag, (float*)d_out, out_size);
}

// round 16
// speedup vs baseline: 1.1876x; 1.1876x over previous
#include <cuda_runtime.h>
#include <cuda_fp16.h>
#include <math.h>
#include <stdint.h>

// Fixed problem shape: n=8192, k=128, h=128
#define N_FIX 8192
#define KDIM 128
#define BM 128
#define BK 32
#define KSPLIT 4
#define KQ (N_FIX / KSPLIT)           // 2048
#define NIT (KQ / BK)                 // 64 iterations per CTA
#define NCTA ((N_FIX / BM) * KSPLIT)  // 256
#define STAGES 4
#define STAGE_BYTES 24576             // 16KB A (128x32 fp32) + 8KB B (32x128 f16)
#define BOFF_IN_STAGE 16384
#define SMEM_BYTES (STAGES * STAGE_BYTES)  // 96KB

// ---------------- device scratch ----------------
__device__ __align__(16) __half g_Cb[(size_t)N_FIX * KDIM];
__device__ float g_d[N_FIX];     // row sums of A (atomic, KSPLIT partials)
__device__ float g_h2[N_FIX];    // ||H_i||^2
__device__ float g_col[KDIM];
__device__ float g_diag[KDIM];
__device__ int g_cnt;

// ---------------- helpers ----------------
__device__ __forceinline__ uint32_t smem_u32(const void* p) {
    uint32_t a;
    asm("{ .reg .u64 t; cvta.to.shared.u64 t, %1; cvt.u32.u64 %0, t; }" : "=r"(a) : "l"(p));
    return a;
}
__device__ __forceinline__ void cp16(uint32_t saddr, const void* gp) {
    unsigned long long g = __cvta_generic_to_global(gp);
    asm volatile("cp.async.cg.shared.global [%0], [%1], 16;" :: "r"(saddr), "l"(g) : "memory");
}
#define CP_COMMIT() asm volatile("cp.async.commit_group;" ::: "memory")
#define CP_WAIT2()  asm volatile("cp.async.wait_group 2;" ::: "memory")

__device__ __forceinline__ uint32_t cvt_h2(float2 v) {
    __half2 h = __floats2half2_rn(v.x, v.y);
    return *reinterpret_cast<uint32_t*>(&h);
}
__device__ __forceinline__ void ldmx4t(uint32_t& r0, uint32_t& r1, uint32_t& r2,
                                       uint32_t& r3, uint32_t addr) {
    asm volatile("ldmatrix.sync.aligned.m8n8.x4.trans.shared.b16 {%0,%1,%2,%3}, [%4];"
                 : "=r"(r0), "=r"(r1), "=r"(r2), "=r"(r3) : "r"(addr));
}
// f16 MMA with f16 accumulators (D/C = 2 regs of f16x2)
__device__ __forceinline__ void mma16816h(uint32_t* d, const uint32_t* a, uint32_t b0,
                                          uint32_t b1) {
    asm volatile(
        "mma.sync.aligned.m16n8k16.row.col.f16.f16.f16.f16 "
        "{%0,%1}, {%2,%3,%4,%5}, {%6,%7}, {%0,%1};"
        : "+r"(d[0]), "+r"(d[1])
        : "r"(a[0]), "r"(a[1]), "r"(a[2]), "r"(a[3]), "r"(b0), "r"(b1));
}

// ---------------- prep: init, C->f16, ||H_i||^2 ----------------
__global__ void __launch_bounds__(256) k_prep(const float* __restrict__ C,
                                              const float* __restrict__ H) {
    const int b = blockIdx.x, tid = threadIdx.x;
    if (b == 0) {
        if (tid < KDIM) { g_col[tid] = 0.0f; g_diag[tid] = 0.0f; }
        if (tid == 0) g_cnt = 0;
    }
    if (tid < 32) g_d[b * 32 + tid] = 0.0f;

    size_t base = ((size_t)b * 256 + tid) * 16;
    const float4* src = reinterpret_cast<const float4*>(C + base);
    uint32_t o[8];
#pragma unroll
    for (int q = 0; q < 4; ++q) {
        float4 v = __ldg(&src[q]);
        o[q * 2 + 0] = cvt_h2(make_float2(v.x, v.y));
        o[q * 2 + 1] = cvt_h2(make_float2(v.z, v.w));
    }
    uint4* dst = reinterpret_cast<uint4*>(g_Cb + base);
    dst[0] = make_uint4(o[0], o[1], o[2], o[3]);
    dst[1] = make_uint4(o[4], o[5], o[6], o[7]);

    const int row = b * 32 + (tid >> 3);
    const float4* hp = reinterpret_cast<const float4*>(H + (size_t)row * KDIM + (tid & 7) * 16);
    float h2 = 0.0f;
#pragma unroll
    for (int q = 0; q < 4; ++q) {
        float4 v = __ldg(&hp[q]);
        h2 += v.x * v.x + v.y * v.y + v.z * v.z + v.w * v.w;
    }
    h2 += __shfl_xor_sync(0xffffffffu, h2, 1);
    h2 += __shfl_xor_sync(0xffffffffu, h2, 2);
    h2 += __shfl_xor_sync(0xffffffffu, h2, 4);
    if ((tid & 7) == 0) g_h2[row] = h2;
}

// ---------------- split-K GEMM (BM=128, f16 acc) + fused reductions + final ----------------
__global__ void __launch_bounds__(256, 2) k_gemm(const float* __restrict__ A,
                                                 const float* __restrict__ C,
                                                 const float* __restrict__ papra,
                                                 const int* __restrict__ flag,
                                                 float* __restrict__ out, int out_size) {
    extern __shared__ __align__(1024) char smem[];
    __shared__ float scol[KDIM], sdiag[KDIM], swarp[8];
    __shared__ int is_last;

    const int tid = threadIdx.x, lane = tid & 31, wid = tid >> 5;
    const int wm = wid & 3, wn = wid >> 2;        // 4 M-warps (m32) x 2 N-warps (n64)
    const int rb = blockIdx.x >> 2;               // row block 0..63
    const int kh = blockIdx.x & 3;                // K quarter
    const int blockRow = rb * BM;
    const int kbase = kh * KQ;
    const uint32_t su = smem_u32(smem);

    if (tid < KDIM) { scol[tid] = 0.0f; sdiag[tid] = 0.0f; }

    // ---- cp.async mapping: A 4 chunks/thread, B 2 chunks/thread ----
    // A tile: 128 rows x 128B, 32B-granular XOR swizzle: addr = r*128 + (c ^ ((r&3)<<5))
    const int rA0 = tid >> 3, cA0 = tid & 7;
    const uint32_t soA0 = (uint32_t)(rA0 * 128 + ((cA0 * 16) ^ ((rA0 & 3) << 5)));
    const float* gA0 = A + (size_t)(blockRow + rA0) * N_FIX + kbase + cA0 * 4;
    // B: 32 k x 256B; 16B XOR swizzle (LDSM-friendly, conflict-free)
    const int kB0 = tid >> 4, cB0 = tid & 15;
    const uint32_t soB0 = (uint32_t)(BOFF_IN_STAGE + kB0 * 256 + ((cB0 * 16) ^ ((kB0 & 7) << 4)));
    const __half* gB0 = g_Cb + (size_t)(kbase + kB0) * KDIM + cB0 * 8;

    // ---- A fragment offsets: rr = wm*32 + (lane>>2) + 8*(q&1); 32B-window XOR
    const int r0 = wm * 32 + (lane >> 2);
    const int cb = (lane & 3) * 2;
    uint32_t aoff[2][4];
#pragma unroll
    for (int kq = 0; kq < 2; ++kq) {
#pragma unroll
        for (int q = 0; q < 4; ++q) {
            int rr = r0 + ((q & 1) ? 8 : 0);
            uint32_t coff = (uint32_t)(kq * 64 + cb * 4 + ((q & 2) ? 32 : 0));
            aoff[kq][q] = (uint32_t)(rr * 128) + (coff ^ ((rr & 3) << 5));
        }
    }
    // ---- B LDSM offsets
    uint32_t boff[4];
    {
        const int mM = lane >> 3, iR = lane & 7;
        const int kkb = (mM & 1) * 8 + iR;
#pragma unroll
        for (int g = 0; g < 4; ++g) {
            int nn = wn * 64 + g * 16 + (mM >> 1) * 8;
            uint32_t off = (uint32_t)(kkb * 256 + nn * 2);
            boff[g] = (uint32_t)BOFF_IN_STAGE + (off ^ ((kkb & 7) << 4));
        }
    }

    // f16 accumulators: [mt][t][2] u32 (each = f16x2)
    uint32_t acc[2][8][2];
#pragma unroll
    for (int mt = 0; mt < 2; ++mt)
#pragma unroll
        for (int t = 0; t < 8; ++t) { acc[mt][t][0] = 0u; acc[mt][t][1] = 0u; }
    float dr[4] = {0.f, 0.f, 0.f, 0.f};  // rows r0 + {0,8,16,24}

    // ---- prologue ----
#pragma unroll
    for (int s = 0; s < STAGES - 1; ++s) {
        uint32_t sb = su + s * STAGE_BYTES;
        size_t kf = (size_t)s * BK;
#pragma unroll
        for (int q = 0; q < 4; ++q)
            cp16(sb + soA0 + q * 4096, gA0 + kf + (size_t)q * 32 * N_FIX);
#pragma unroll
        for (int q = 0; q < 2; ++q)
            cp16(sb + soB0 + q * 4096, gB0 + (kf + (size_t)q * 16) * KDIM);
        CP_COMMIT();
    }

    // ---- main loop ----
    for (int it = 0; it < NIT; ++it) {
        CP_WAIT2();
        __syncthreads();
        const uint32_t stg = (uint32_t)((it & (STAGES - 1)) * STAGE_BYTES);

#pragma unroll
        for (int kq = 0; kq < 2; ++kq) {
            uint32_t ra[2][4];
#pragma unroll
            for (int mt = 0; mt < 2; ++mt) {
                float2 fA[4];
#pragma unroll
                for (int q = 0; q < 4; ++q)
                    fA[q] = *reinterpret_cast<const float2*>(
                        smem + stg + aoff[kq][q] + mt * 2048);
                dr[2 * mt + 0] += (fA[0].x + fA[0].y) + (fA[2].x + fA[2].y);
                dr[2 * mt + 1] += (fA[1].x + fA[1].y) + (fA[3].x + fA[3].y);
#pragma unroll
                for (int q = 0; q < 4; ++q) ra[mt][q] = cvt_h2(fA[q]);
            }
#pragma unroll
            for (int g = 0; g < 4; ++g) {
                uint32_t b0, b1, b2, b3;
                ldmx4t(b0, b1, b2, b3, su + stg + boff[g] + kq * 4096);
                mma16816h(acc[0][2 * g], ra[0], b0, b1);
                mma16816h(acc[0][2 * g + 1], ra[0], b2, b3);
                mma16816h(acc[1][2 * g], ra[1], b0, b1);
                mma16816h(acc[1][2 * g + 1], ra[1], b2, b3);
            }
        }

        int nxt = it + (STAGES - 1);
        if (nxt < NIT) {
            uint32_t sb = su + (nxt & (STAGES - 1)) * STAGE_BYTES;
            size_t kf = (size_t)nxt * BK;
#pragma unroll
            for (int q = 0; q < 4; ++q)
                cp16(sb + soA0 + q * 4096, gA0 + kf + (size_t)q * 32 * N_FIX);
#pragma unroll
            for (int q = 0; q < 2; ++q)
                cp16(sb + soB0 + q * 4096, gB0 + (kf + (size_t)q * 16) * KDIM);
        }
        CP_COMMIT();
    }

    // ---- partial row sums of A (exact fp32; wn==0 warps only) ----
    if (wn == 0) {
#pragma unroll
        for (int m = 0; m < 4; ++m) {
            float s = dr[m];
            s += __shfl_xor_sync(0xffffffffu, s, 1);
            s += __shfl_xor_sync(0xffffffffu, s, 2);
            if ((lane & 3) == 0) atomicAdd(&g_d[blockRow + r0 + ((m & 1) ? 8 : 0) + (m >> 1) * 16], s);
        }
    }

    // ---- colsum(M) and diag partials (unpack f16 acc) ----
#pragma unroll
    for (int mt = 0; mt < 2; ++mt)
#pragma unroll
    for (int t = 0; t < 8; ++t) {
        const int cbase = wn * 64 + t * 8 + cb;
        const int row = blockRow + r0 + mt * 16;
        float2 c0 = *reinterpret_cast<const float2*>(C + (size_t)row * KDIM + cbase);
        float2 c1 = *reinterpret_cast<const float2*>(C + (size_t)(row + 8) * KDIM + cbase);
        float2 m0 = __half22float2(*reinterpret_cast<__half2*>(&acc[mt][t][0]));  // row r
        float2 m1 = __half22float2(*reinterpret_cast<__half2*>(&acc[mt][t][1]));  // row r+8
        float cs0 = m0.x + m1.x;
        float cs1 = m0.y + m1.y;
        float ds0 = c0.x * m0.x + c1.x * m1.x;
        float ds1 = c0.y * m0.y + c1.y * m1.y;
#pragma unroll
        for (int o = 4; o <= 16; o <<= 1) {
            cs0 += __shfl_xor_sync(0xffffffffu, cs0, o);
            cs1 += __shfl_xor_sync(0xffffffffu, cs1, o);
            ds0 += __shfl_xor_sync(0xffffffffu, ds0, o);
            ds1 += __shfl_xor_sync(0xffffffffu, ds1, o);
        }
        if ((lane >> 2) == 0) {
            atomicAdd(&scol[cbase], cs0);
            atomicAdd(&scol[cbase + 1], cs1);
            atomicAdd(&sdiag[cbase], ds0);
            atomicAdd(&sdiag[cbase + 1], ds1);
        }
    }
    __syncthreads();
    if (tid < KDIM) {
        atomicAdd(&g_col[tid], scol[tid]);
        atomicAdd(&g_diag[tid], sdiag[tid]);
    }

    // ---- last CTA: sA, h_part, entropy, output ----
    if (tid == 0) {
        __threadfence();
        int c = atomicAdd(&g_cnt, 1);
        is_last = (c == NCTA - 1);
    }
    __syncthreads();
    if (is_last) {
        float a1 = 0.0f, a2 = 0.0f;
        for (int i = tid; i < N_FIX; i += 256) {
            float d = __ldcg(&g_d[i]);
            a1 += d * __ldcg(&g_h2[i]);
            a2 += d;
        }
#pragma unroll
        for (int o = 16; o > 0; o >>= 1) {
            a1 += __shfl_xor_sync(0xffffffffu, a1, o);
            a2 += __shfl_xor_sync(0xffffffffu, a2, o);
        }
        if (lane == 0) { swarp[wid] = a1; scol[wid] = a2; }
        __syncthreads();
        float hp = 0.0f, sA = 0.0f;
#pragma unroll
        for (int w = 0; w < 8; ++w) { hp += swarp[w]; sA += scol[w]; }

        float t = 0.0f;
        if (tid < KDIM) {
            float dg = __ldcg(&g_diag[tid]);
            float cl = __ldcg(&g_col[tid]);
            t = dg * log2f(cl / sA + 1e-40f);
        }
#pragma unroll
        for (int o = 16; o > 0; o >>= 1) t += __shfl_xor_sync(0xffffffffu, t, o);
        __syncthreads();
        if (lane == 0) sdiag[wid] = t;
        __syncthreads();
        if (tid == 0) {
            float total = (sdiag[0] + sdiag[1] + sdiag[2] + sdiag[3]) / sA;
            int fl = flag ? *flag : 20;
            float pw = papra ? *papra : 1.0f;
            if (fl > 10) total += pw * hp;
            out[0] = total;
            if (out_size > 1) out[1] = hp;
        }
    }
}

extern "C" void kernel_launch(void* const* d_in, const int* in_sizes, int n_in,
                              void* d_out, int out_size) {
    const float* A = (const float*)d_in[0];
    const float* C = (const float*)d_in[1];
    const float* H = (const float*)d_in[2];
    const float* papra = (n_in > 3) ? (const float*)d_in[3] : nullptr;
    const int* flag = (n_in > 4) ? (const int*)d_in[4] : nullptr;

    cudaFuncSetAttribute(k_gemm, cudaFuncAttributeMaxDynamicSharedMemorySize, SMEM_BYTES);

    k_prep<<<N_FIX / 32, 256>>>(C, H);
    k_gemm<<<NCTA, 256, SMEM_BYTES>>>(A, C, papra, flag, (float*)d_out, out_size);
}